// round 10
// baseline (speedup 1.0000x reference)
#include <cuda_runtime.h>
#include <float.h>

#define NOFF    44
#define NDENSE  33
#define NSPARSE 11
#define HD      64
#define SEQ     8192
#define HNUM    16
#define BNUM    2
#define TPB     128
#define NWARP   (TPB / 32)
#define QT      4                  // queries per octet
#define QPW     (4 * QT)           // 16 queries per warp
#define QPB     (NWARP * QPW)      // 64 queries per block
#define WPAD    49                 // float2 row width (36 dense + 11 sparse + pad; 49 -> +8 banks per 4 rows)
#define SDENSE  36                 // dense shifted columns 0..35
#define SCOL    36                 // sparse weights at cols 36..46

typedef unsigned long long ull;

__constant__ int c_soff[NSPARSE] = {48,64,96,128,192,256,384,512,768,1024,1536};

// ---- packed f32x2 helpers (Blackwell FFMA2 path, PTX-only) ----
__device__ __forceinline__ ull f2fma(ull a, ull b, ull c) {
    ull d; asm("fma.rn.f32x2 %0, %1, %2, %3;" : "=l"(d) : "l"(a), "l"(b), "l"(c)); return d;
}
__device__ __forceinline__ ull f2add(ull a, ull b) {
    ull d; asm("add.rn.f32x2 %0, %1, %2;" : "=l"(d) : "l"(a), "l"(b)); return d;
}
__device__ __forceinline__ ull f2mul(ull a, ull b) {
    ull d; asm("mul.rn.f32x2 %0, %1, %2;" : "=l"(d) : "l"(a), "l"(b)); return d;
}
__device__ __forceinline__ ull f2pack(float lo, float hi) {
    ull d; asm("mov.b64 %0, {%1, %2};" : "=l"(d) : "f"(lo), "f"(hi)); return d;
}
__device__ __forceinline__ float2 f2unpack(ull v) {
    float lo, hi; asm("mov.b64 {%0, %1}, %2;" : "=f"(lo), "=f"(hi) : "l"(v));
    return make_float2(lo, hi);
}

__device__ __forceinline__ float dot8p(ulonglong2 qa, ulonglong2 qb,
                                       ulonglong2 b0, ulonglong2 b1) {
    ull acc = f2mul(qa.x, b0.x);
    acc = f2fma(qa.y, b0.y, acc);
    acc = f2fma(qb.x, b1.x, acc);
    acc = f2fma(qb.y, b1.y, acc);
    float2 r = f2unpack(acc);
    return r.x + r.y;
}

__device__ __forceinline__ ulonglong2 u2add(ulonglong2 a, ulonglong2 b) {
    ulonglong2 r; r.x = f2add(a.x, b.x); r.y = f2add(a.y, b.y); return r;
}

__device__ __forceinline__ float red8(float p) {
    p += __shfl_xor_sync(0xffffffffu, p, 1);
    p += __shfl_xor_sync(0xffffffffu, p, 2);
    p += __shfl_xor_sync(0xffffffffu, p, 4);
    return p;
}

__global__ __launch_bounds__(TPB, 5)
void dsqg_attn_kernel(const float* __restrict__ q,
                      const float* __restrict__ k,
                      const float* __restrict__ v,
                      const float* __restrict__ pb,
                      const float* __restrict__ se,
                      const float* __restrict__ ph,
                      float* __restrict__ out) {
    const int lane = threadIdx.x & 31;
    const int wid  = threadIdx.x >> 5;
    const int o    = lane >> 3;      // octet id (0..3)
    const int ln8  = lane & 7;       // lane within octet

    __shared__ ulonglong2 s_se[NOFF * 16];
    __shared__ float  s_pb[NOFF];
    __shared__ float  s_cos[NOFF];
    __shared__ float  s_sin[NOFF];
    // union region: pass1 stores raw scores (float view, cols 0..43);
    // softmax rewrites as shifted (w*cos, w*sin) float2 (cols 0..46).
    __shared__ float2 s_w[QPB][WPAD];

    for (int i = threadIdx.x; i < NOFF * 16; i += TPB)
        s_se[i] = ((const ulonglong2*)se)[i];
    if (threadIdx.x < NOFF) {
        const int h0 = blockIdx.y;
        s_pb[threadIdx.x] = pb[threadIdx.x * HNUM + h0];
        float p = ph[threadIdx.x * HNUM + h0];
        s_cos[threadIdx.x] = cosf(p);
        s_sin[threadIdx.x] = sinf(p);
    }
    __syncthreads();

    const int h = blockIdx.y;
    const int b = blockIdx.z;
    const size_t bh = ((size_t)b * HNUM + h) * SEQ;
    const ulonglong2* kb = (const ulonglong2*)(k + bh * HD);
    const ulonglong2* vb = (const ulonglong2*)(v + bh * HD);

    const int ql0 = wid * QPW + o * QT;
    const int n0  = blockIdx.x * QPB + ql0;
    const int n3  = n0 + 3;

    const float sc = 0.125f;   // 1/sqrt(64)

    // ================= pass 1: dense+sparse scores (4-deep k FIFO, packed) =================
    {
        ulonglong2 qa[QT], qbr[QT];
        #pragma unroll
        for (int t = 0; t < QT; t++) {
            const ulonglong2* qp = (const ulonglong2*)(q + (bh + (size_t)(n0 + t)) * HD);
            qa[t]  = qp[ln8];
            qbr[t] = qp[8 + ln8];
        }

        ulonglong2 f0[4], f1[4];
        #pragma unroll
        for (int j = 0; j < 4; j++) {
            const ulonglong2* kr = kb + (size_t)(n3 - j) * 16;
            f0[j] = kr[ln8];
            f1[j] = kr[8 + ln8];
        }
        #pragma unroll 3
        for (int d = 0; d < NDENSE; d++) {
            ulonglong2 e0 = s_se[d * 16 + ln8];
            ulonglong2 e1 = s_se[d * 16 + 8 + ln8];
            float p3 = dot8p(qa[3], qbr[3], u2add(f0[0], e0), u2add(f1[0], e1));
            float p2 = dot8p(qa[2], qbr[2], u2add(f0[1], e0), u2add(f1[1], e1));
            float p1 = dot8p(qa[1], qbr[1], u2add(f0[2], e0), u2add(f1[2], e1));
            float p0 = dot8p(qa[0], qbr[0], u2add(f0[3], e0), u2add(f1[3], e1));
            int rn = n0 - d - 1;
            int rc = rn < 0 ? 0 : rn;
            f0[0] = f0[1]; f1[0] = f1[1];
            f0[1] = f0[2]; f1[1] = f1[2];
            f0[2] = f0[3]; f1[2] = f1[3];
            {
                const ulonglong2* kr = kb + (size_t)rc * 16;
                f0[3] = kr[ln8];
                f1[3] = kr[8 + ln8];
            }
            p3 = red8(p3); p2 = red8(p2); p1 = red8(p1); p0 = red8(p0);
            if (ln8 == 0) {
                float bias = s_pb[d];
                ((float*)s_w[ql0 + 3])[d] = (n3     >= d) ? fmaf(p3, sc, bias) : -1e30f;
                ((float*)s_w[ql0 + 2])[d] = (n0 + 2 >= d) ? fmaf(p2, sc, bias) : -1e30f;
                ((float*)s_w[ql0 + 1])[d] = (n0 + 1 >= d) ? fmaf(p1, sc, bias) : -1e30f;
                ((float*)s_w[ql0    ])[d] = (n0     >= d) ? fmaf(p0, sc, bias) : -1e30f;
            }
        }

        #pragma unroll
        for (int i = 0; i < NSPARSE; i++) {
            const int d  = c_soff[i];
            const int io = NDENSE + i;
            ulonglong2 e0 = s_se[io * 16 + ln8];
            ulonglong2 e1 = s_se[io * 16 + 8 + ln8];
            float ps_[QT];
            #pragma unroll
            for (int t = 0; t < QT; t++) {
                int r  = n0 + t - d;
                int rc = r < 0 ? 0 : r;
                const ulonglong2* kr = kb + (size_t)rc * 16;
                ps_[t] = dot8p(qa[t], qbr[t], u2add(kr[ln8], e0), u2add(kr[8 + ln8], e1));
            }
            #pragma unroll
            for (int t = 0; t < QT; t++) ps_[t] = red8(ps_[t]);
            if (ln8 == 0) {
                float bias = s_pb[io];
                #pragma unroll
                for (int t = 0; t < QT; t++)
                    ((float*)s_w[ql0 + t])[io] = (n0 + t >= d) ? fmaf(ps_[t], sc, bias) : -1e30f;
            }
        }
    }
    __syncwarp();

    // ====== softmax (2 lanes/query, 22 offsets each) + shifted weight write ======
    // dense offset d of query (local index t) -> column j = d + 3 - t; sparse d -> column d + 3.
    {
        const int qloc = wid * QPW + (lane & 15);
        const int tq   = qloc & 3;               // query index within its octet
        const int half = lane >> 4;
        const int base = half * 22;
        float vals[22];
        float vmax = -FLT_MAX;
        #pragma unroll
        for (int t = 0; t < 22; t++) {
            vals[t] = ((float*)s_w[qloc])[base + t];
            vmax = fmaxf(vmax, vals[t]);
        }
        vmax = fmaxf(vmax, __shfl_xor_sync(0xffffffffu, vmax, 16));
        float sum = 0.f;
        #pragma unroll
        for (int t = 0; t < 22; t++) {
            vals[t] = __expf(vals[t] - vmax);
            sum += vals[t];
        }
        sum += __shfl_xor_sync(0xffffffffu, sum, 16);
        const float inv = 1.0f / sum;
        #pragma unroll
        for (int t = 0; t < 22; t++) {
            const int d = base + t;
            float w = vals[t] * inv;
            int col = d + 3 - ((d < NDENSE) ? tq : 0);
            s_w[qloc][col] = make_float2(w * s_cos[d], w * s_sin[d]);
        }
        // zero-fill the 3 shifted-out dense columns of this query's row
        if (half == 0) {
            #pragma unroll
            for (int z = 0; z < 3; z++)
                if (z < 3 - tq) s_w[qloc][z] = make_float2(0.f, 0.f);
        } else {
            #pragma unroll
            for (int z = 33; z < 36; z++)
                if (z >= 36 - tq) s_w[qloc][z] = make_float2(0.f, 0.f);
        }
    }
    __syncwarp();

    // ========== pass 2: row iteration, A = sum(wc*v), B = sum(ws*v), rotate at end ==========
    ulonglong2 A0[QT], A1[QT], B0[QT], B1[QT];
    #pragma unroll
    for (int t = 0; t < QT; t++) {
        A0[t].x = A0[t].y = A1[t].x = A1[t].y = 0ull;
        B0[t].x = B0[t].y = B1[t].x = B1[t].y = 0ull;
    }

    // dense: row r = n3 - j serves query t at column j (weight already shifted; zeros self-mask)
    #pragma unroll 4
    for (int j = 0; j < SDENSE; j++) {
        int r  = n3 - j;
        int rc = r < 0 ? 0 : r;
        const ulonglong2* vr = vb + (size_t)rc * 16;
        ulonglong2 v0 = vr[ln8];
        ulonglong2 v1 = vr[8 + ln8];
        #pragma unroll
        for (int t = 0; t < QT; t++) {
            float2 w = s_w[ql0 + t][j];
            ull pcp = f2pack(w.x, w.x);
            ull psp = f2pack(w.y, w.y);
            A0[t].x = f2fma(v0.x, pcp, A0[t].x);
            A0[t].y = f2fma(v0.y, pcp, A0[t].y);
            A1[t].x = f2fma(v1.x, pcp, A1[t].x);
            A1[t].y = f2fma(v1.y, pcp, A1[t].y);
            B0[t].x = f2fma(v0.x, psp, B0[t].x);
            B0[t].y = f2fma(v0.y, psp, B0[t].y);
            B1[t].x = f2fma(v1.x, psp, B1[t].x);
            B1[t].y = f2fma(v1.y, psp, B1[t].y);
        }
    }

    // sparse (w == 0 self-masks)
    #pragma unroll
    for (int i = 0; i < NSPARSE; i++) {
        const int d = c_soff[i];
        #pragma unroll
        for (int t = 0; t < QT; t++) {
            int r  = n0 + t - d;
            int rc = r < 0 ? 0 : r;
            float2 w = s_w[ql0 + t][SCOL + i];
            ull pcp = f2pack(w.x, w.x);
            ull psp = f2pack(w.y, w.y);
            const ulonglong2* vr = vb + (size_t)rc * 16;
            ulonglong2 v0 = vr[ln8];
            ulonglong2 v1 = vr[8 + ln8];
            A0[t].x = f2fma(v0.x, pcp, A0[t].x);
            A0[t].y = f2fma(v0.y, pcp, A0[t].y);
            A1[t].x = f2fma(v1.x, pcp, A1[t].x);
            A1[t].y = f2fma(v1.y, pcp, A1[t].y);
            B0[t].x = f2fma(v0.x, psp, B0[t].x);
            B0[t].y = f2fma(v0.y, psp, B0[t].y);
            B1[t].x = f2fma(v1.x, psp, B1[t].x);
            B1[t].y = f2fma(v1.y, psp, B1[t].y);
        }
    }

    // ================= final rotation + store =================
    #pragma unroll
    for (int t = 0; t < QT; t++) {
        float4* op = (float4*)(out + (bh + (size_t)(n0 + t)) * HD);
        float2 a0 = f2unpack(A0[t].x), b0 = f2unpack(B0[t].x);
        float2 a1 = f2unpack(A0[t].y), b1 = f2unpack(B0[t].y);
        float2 a2 = f2unpack(A1[t].x), b2 = f2unpack(B1[t].x);
        float2 a3 = f2unpack(A1[t].y), b3 = f2unpack(B1[t].y);
        float4 r0, r1;
        r0.x = a0.x - b0.y;  r0.y = a0.y + b0.x;
        r0.z = a1.x - b1.y;  r0.w = a1.y + b1.x;
        r1.x = a2.x - b2.y;  r1.y = a2.y + b2.x;
        r1.z = a3.x - b3.y;  r1.w = a3.y + b3.x;
        op[ln8]     = r0;
        op[8 + ln8] = r1;
    }
}

extern "C" void kernel_launch(void* const* d_in, const int* in_sizes, int n_in,
                              void* d_out, int out_size) {
    const float* q  = (const float*)d_in[0];
    const float* k  = (const float*)d_in[1];
    const float* v  = (const float*)d_in[2];
    const float* pb = (const float*)d_in[3];
    const float* se = (const float*)d_in[4];
    const float* ph = (const float*)d_in[5];
    float* out = (float*)d_out;

    dim3 grid(SEQ / QPB, HNUM, BNUM);
    dsqg_attn_kernel<<<grid, TPB>>>(q, k, v, pb, se, ph, out);
}

// round 11
// speedup vs baseline: 1.1391x; 1.1391x over previous
#include <cuda_runtime.h>
#include <float.h>

#define NOFF    44
#define NDENSE  33
#define NSPARSE 11
#define HD      64
#define SEQ     8192
#define HNUM    16
#define BNUM    2
#define TPB     128
#define NWARP   (TPB / 32)
#define QT      4                  // queries per octet
#define QPW     (4 * QT)           // 16 queries per warp
#define QPB     (NWARP * QPW)      // 64 queries per block
#define WPAD    45                 // float4 row width (44 + pad, odd stride -> conflict-free octet quads)
#define XSPLIT  24                 // blocks with xb >= XSPLIT never clamp (24*64 = 1536 = max offset)

typedef unsigned long long ull;

__constant__ int c_soff[NSPARSE] = {48,64,96,128,192,256,384,512,768,1024,1536};

// ---- packed f32x2 helpers (Blackwell FFMA2 path, PTX-only) ----
__device__ __forceinline__ ull f2fma(ull a, ull b, ull c) {
    ull d; asm("fma.rn.f32x2 %0, %1, %2, %3;" : "=l"(d) : "l"(a), "l"(b), "l"(c)); return d;
}
__device__ __forceinline__ ull f2add(ull a, ull b) {
    ull d; asm("add.rn.f32x2 %0, %1, %2;" : "=l"(d) : "l"(a), "l"(b)); return d;
}
__device__ __forceinline__ ull f2mul(ull a, ull b) {
    ull d; asm("mul.rn.f32x2 %0, %1, %2;" : "=l"(d) : "l"(a), "l"(b)); return d;
}
__device__ __forceinline__ float2 f2unpack(ull v) {
    float lo, hi; asm("mov.b64 {%0, %1}, %2;" : "=f"(lo), "=f"(hi) : "l"(v));
    return make_float2(lo, hi);
}

__device__ __forceinline__ float dot8p(ulonglong2 qa, ulonglong2 qb,
                                       ulonglong2 b0, ulonglong2 b1) {
    ull acc = f2mul(qa.x, b0.x);
    acc = f2fma(qa.y, b0.y, acc);
    acc = f2fma(qb.x, b1.x, acc);
    acc = f2fma(qb.y, b1.y, acc);
    float2 r = f2unpack(acc);
    return r.x + r.y;
}

__device__ __forceinline__ ulonglong2 u2add(ulonglong2 a, ulonglong2 b) {
    ulonglong2 r; r.x = f2add(a.x, b.x); r.y = f2add(a.y, b.y); return r;
}

__device__ __forceinline__ float red8(float p) {
    p += __shfl_xor_sync(0xffffffffu, p, 1);
    p += __shfl_xor_sync(0xffffffffu, p, 2);
    p += __shfl_xor_sync(0xffffffffu, p, 4);
    return p;
}

template<bool SAFE>
__global__ __launch_bounds__(TPB, 4)
void dsqg_attn_kernel(int xbase,
                      const float* __restrict__ q,
                      const float* __restrict__ k,
                      const float* __restrict__ v,
                      const float* __restrict__ pb,
                      const float* __restrict__ se,
                      const float* __restrict__ ph,
                      float* __restrict__ out) {
    const int lane = threadIdx.x & 31;
    const int wid  = threadIdx.x >> 5;
    const int o    = lane >> 3;      // octet id (0..3)
    const int ln8  = lane & 7;       // lane within octet

    __shared__ float  s_pb[NOFF];
    __shared__ float  s_cos[NOFF];
    __shared__ float  s_sin[NOFF];
    // union: pass1 stores raw scores as float (cols 0..43 of each 720B row);
    // softmax rewrites rows as float4 (wc,wc,ws,ws) per offset.
    __shared__ float4 s_w[QPB][WPAD];

    if (threadIdx.x < NOFF) {
        const int h0 = blockIdx.y;
        s_pb[threadIdx.x] = pb[threadIdx.x * HNUM + h0];
        float p = ph[threadIdx.x * HNUM + h0];
        s_cos[threadIdx.x] = cosf(p);
        s_sin[threadIdx.x] = sinf(p);
    }
    __syncthreads();

    const int h = blockIdx.y;
    const int b = blockIdx.z;
    const size_t bh = ((size_t)b * HNUM + h) * SEQ;
    const ulonglong2* kb = (const ulonglong2*)(k + bh * HD);
    const ulonglong2* vb = (const ulonglong2*)(v + bh * HD);
    const ulonglong2* sep = (const ulonglong2*)se;

    const int ql0 = wid * QPW + o * QT;
    const int n0  = (blockIdx.x + xbase) * QPB + ql0;
    const int n3  = n0 + 3;

    const float sc = 0.125f;   // 1/sqrt(64)

    // ================= pass 1: dense+sparse scores (4-deep k FIFO, packed) =================
    {
        ulonglong2 qa[QT], qbr[QT];
        #pragma unroll
        for (int t = 0; t < QT; t++) {
            const ulonglong2* qp = (const ulonglong2*)(q + (bh + (size_t)(n0 + t)) * HD);
            qa[t]  = qp[ln8];
            qbr[t] = qp[8 + ln8];
        }

        ulonglong2 f0[4], f1[4];
        #pragma unroll
        for (int j = 0; j < 4; j++) {
            const ulonglong2* kr = kb + (size_t)(n3 - j) * 16;
            f0[j] = kr[ln8];
            f1[j] = kr[8 + ln8];
        }
        const ulonglong2* kwalk = kb + (size_t)(n0 - 1) * 16;   // row n0-d-1 at d=0 (SAFE path)
        const ulonglong2* sewalk = sep;
        #pragma unroll 3
        for (int d = 0; d < NDENSE; d++) {
            ulonglong2 e0 = __ldg(&sewalk[ln8]);
            ulonglong2 e1 = __ldg(&sewalk[8 + ln8]);
            sewalk += 16;
            float p3 = dot8p(qa[3], qbr[3], u2add(f0[0], e0), u2add(f1[0], e1));
            float p2 = dot8p(qa[2], qbr[2], u2add(f0[1], e0), u2add(f1[1], e1));
            float p1 = dot8p(qa[1], qbr[1], u2add(f0[2], e0), u2add(f1[2], e1));
            float p0 = dot8p(qa[0], qbr[0], u2add(f0[3], e0), u2add(f1[3], e1));
            f0[0] = f0[1]; f1[0] = f1[1];
            f0[1] = f0[2]; f1[1] = f1[2];
            f0[2] = f0[3]; f1[2] = f1[3];
            if (SAFE) {
                f0[3] = kwalk[ln8];
                f1[3] = kwalk[8 + ln8];
                kwalk -= 16;
            } else {
                int rn = n0 - d - 1;
                int rc = rn < 0 ? 0 : rn;
                const ulonglong2* kr = kb + (size_t)rc * 16;
                f0[3] = kr[ln8];
                f1[3] = kr[8 + ln8];
            }
            p3 = red8(p3); p2 = red8(p2); p1 = red8(p1); p0 = red8(p0);
            if (ln8 == 0) {
                float bias = s_pb[d];
                if (SAFE) {
                    ((float*)&s_w[ql0 + 3][0])[d] = fmaf(p3, sc, bias);
                    ((float*)&s_w[ql0 + 2][0])[d] = fmaf(p2, sc, bias);
                    ((float*)&s_w[ql0 + 1][0])[d] = fmaf(p1, sc, bias);
                    ((float*)&s_w[ql0    ][0])[d] = fmaf(p0, sc, bias);
                } else {
                    ((float*)&s_w[ql0 + 3][0])[d] = (n3     >= d) ? fmaf(p3, sc, bias) : -1e30f;
                    ((float*)&s_w[ql0 + 2][0])[d] = (n0 + 2 >= d) ? fmaf(p2, sc, bias) : -1e30f;
                    ((float*)&s_w[ql0 + 1][0])[d] = (n0 + 1 >= d) ? fmaf(p1, sc, bias) : -1e30f;
                    ((float*)&s_w[ql0    ][0])[d] = (n0     >= d) ? fmaf(p0, sc, bias) : -1e30f;
                }
            }
        }

        #pragma unroll
        for (int i = 0; i < NSPARSE; i++) {
            const int d  = c_soff[i];
            const int io = NDENSE + i;
            ulonglong2 e0 = __ldg(&sep[io * 16 + ln8]);
            ulonglong2 e1 = __ldg(&sep[io * 16 + 8 + ln8]);
            float ps_[QT];
            #pragma unroll
            for (int t = 0; t < QT; t++) {
                int r  = n0 + t - d;
                int rc = SAFE ? r : (r < 0 ? 0 : r);
                const ulonglong2* kr = kb + (size_t)rc * 16;
                ps_[t] = dot8p(qa[t], qbr[t], u2add(kr[ln8], e0), u2add(kr[8 + ln8], e1));
            }
            #pragma unroll
            for (int t = 0; t < QT; t++) ps_[t] = red8(ps_[t]);
            if (ln8 == 0) {
                float bias = s_pb[io];
                #pragma unroll
                for (int t = 0; t < QT; t++) {
                    float sv = fmaf(ps_[t], sc, bias);
                    if (!SAFE && (n0 + t < d)) sv = -1e30f;
                    ((float*)&s_w[ql0 + t][0])[io] = sv;
                }
            }
        }
    }
    __syncwarp();

    // ====== softmax (2 lanes/query, 22 offsets each); write (wc,wc,ws,ws) float4 ======
    {
        const int qloc = wid * QPW + (lane & 15);
        const int half = lane >> 4;
        const int base = half * 22;
        float vals[22];
        float vmax = -FLT_MAX;
        #pragma unroll
        for (int t = 0; t < 22; t++) {
            vals[t] = ((const float*)&s_w[qloc][0])[base + t];
            vmax = fmaxf(vmax, vals[t]);
        }
        vmax = fmaxf(vmax, __shfl_xor_sync(0xffffffffu, vmax, 16));   // all reads done after this
        float sum = 0.f;
        #pragma unroll
        for (int t = 0; t < 22; t++) {
            vals[t] = __expf(vals[t] - vmax);
            sum += vals[t];
        }
        sum += __shfl_xor_sync(0xffffffffu, sum, 16);
        const float inv = 1.0f / sum;
        #pragma unroll
        for (int t = 0; t < 22; t++) {
            const int d = base + t;
            float w  = vals[t] * inv;
            float wc = w * s_cos[d];
            float ws = w * s_sin[d];
            s_w[qloc][d] = make_float4(wc, wc, ws, ws);
        }
    }
    __syncwarp();

    // ========== pass 2: offset iteration, 4-deep v FIFO, A/B accumulate, rotate at end ==========
    ulonglong2 A0[QT], A1[QT], B0[QT], B1[QT];
    #pragma unroll
    for (int t = 0; t < QT; t++) {
        A0[t].x = A0[t].y = A1[t].x = A1[t].y = 0ull;
        B0[t].x = B0[t].y = B1[t].x = B1[t].y = 0ull;
    }

    {
        ulonglong2 f0[4], f1[4];
        #pragma unroll
        for (int j = 0; j < 4; j++) {
            const ulonglong2* vr = vb + (size_t)(n3 - j) * 16;
            f0[j] = vr[ln8];
            f1[j] = vr[8 + ln8];
        }
        const ulonglong2* vwalk = vb + (size_t)(n0 - 1) * 16;
        #pragma unroll 3
        for (int d = 0; d < NDENSE; d++) {
            #pragma unroll
            for (int t = 0; t < QT; t++) {
                ulonglong2 wp = *(const ulonglong2*)&s_w[ql0 + t][d];   // LDS.128: (wc,wc | ws,ws)
                A0[t].x = f2fma(f0[3 - t].x, wp.x, A0[t].x);
                A0[t].y = f2fma(f0[3 - t].y, wp.x, A0[t].y);
                A1[t].x = f2fma(f1[3 - t].x, wp.x, A1[t].x);
                A1[t].y = f2fma(f1[3 - t].y, wp.x, A1[t].y);
                B0[t].x = f2fma(f0[3 - t].x, wp.y, B0[t].x);
                B0[t].y = f2fma(f0[3 - t].y, wp.y, B0[t].y);
                B1[t].x = f2fma(f1[3 - t].x, wp.y, B1[t].x);
                B1[t].y = f2fma(f1[3 - t].y, wp.y, B1[t].y);
            }
            f0[0] = f0[1]; f1[0] = f1[1];
            f0[1] = f0[2]; f1[1] = f1[2];
            f0[2] = f0[3]; f1[2] = f1[3];
            if (SAFE) {
                f0[3] = vwalk[ln8];
                f1[3] = vwalk[8 + ln8];
                vwalk -= 16;
            } else {
                int rn = n0 - d - 1;
                int rc = rn < 0 ? 0 : rn;
                const ulonglong2* vr = vb + (size_t)rc * 16;
                f0[3] = vr[ln8];
                f1[3] = vr[8 + ln8];
            }
        }
    }

    // sparse (w == 0 self-masks in CLAMP blocks)
    #pragma unroll
    for (int i = 0; i < NSPARSE; i++) {
        const int d  = c_soff[i];
        const int io = NDENSE + i;
        #pragma unroll
        for (int t = 0; t < QT; t++) {
            int r  = n0 + t - d;
            int rc = SAFE ? r : (r < 0 ? 0 : r);
            ulonglong2 wp = *(const ulonglong2*)&s_w[ql0 + t][io];
            const ulonglong2* vr = vb + (size_t)rc * 16;
            ulonglong2 v0 = vr[ln8];
            ulonglong2 v1 = vr[8 + ln8];
            A0[t].x = f2fma(v0.x, wp.x, A0[t].x);
            A0[t].y = f2fma(v0.y, wp.x, A0[t].y);
            A1[t].x = f2fma(v1.x, wp.x, A1[t].x);
            A1[t].y = f2fma(v1.y, wp.x, A1[t].y);
            B0[t].x = f2fma(v0.x, wp.y, B0[t].x);
            B0[t].y = f2fma(v0.y, wp.y, B0[t].y);
            B1[t].x = f2fma(v1.x, wp.y, B1[t].x);
            B1[t].y = f2fma(v1.y, wp.y, B1[t].y);
        }
    }

    // ================= final rotation + store =================
    #pragma unroll
    for (int t = 0; t < QT; t++) {
        float4* op = (float4*)(out + (bh + (size_t)(n0 + t)) * HD);
        float2 a0 = f2unpack(A0[t].x), b0 = f2unpack(B0[t].x);
        float2 a1 = f2unpack(A0[t].y), b1 = f2unpack(B0[t].y);
        float2 a2 = f2unpack(A1[t].x), b2 = f2unpack(B1[t].x);
        float2 a3 = f2unpack(A1[t].y), b3 = f2unpack(B1[t].y);
        float4 r0, r1;
        r0.x = a0.x - b0.y;  r0.y = a0.y + b0.x;
        r0.z = a1.x - b1.y;  r0.w = a1.y + b1.x;
        r1.x = a2.x - b2.y;  r1.y = a2.y + b2.x;
        r1.z = a3.x - b3.y;  r1.w = a3.y + b3.x;
        op[ln8]     = r0;
        op[8 + ln8] = r1;
    }
}

extern "C" void kernel_launch(void* const* d_in, const int* in_sizes, int n_in,
                              void* d_out, int out_size) {
    const float* q  = (const float*)d_in[0];
    const float* k  = (const float*)d_in[1];
    const float* v  = (const float*)d_in[2];
    const float* pb = (const float*)d_in[3];
    const float* se = (const float*)d_in[4];
    const float* ph = (const float*)d_in[5];
    float* out = (float*)d_out;

    const int NXB = SEQ / QPB;   // 128
    dim3 gridC(XSPLIT, HNUM, BNUM);           // clamped blocks [0, 24)
    dim3 gridS(NXB - XSPLIT, HNUM, BNUM);     // safe blocks [24, 128)
    dsqg_attn_kernel<false><<<gridC, TPB>>>(0,      q, k, v, pb, se, ph, out);
    dsqg_attn_kernel<true ><<<gridS, TPB>>>(XSPLIT, q, k, v, pb, se, ph, out);
}

// round 12
// speedup vs baseline: 1.2177x; 1.0689x over previous
#include <cuda_runtime.h>
#include <float.h>

#define NOFF    44
#define NDENSE  33
#define NSPARSE 11
#define HD      64
#define SEQ     8192
#define HNUM    16
#define BNUM    2
#define TPB     128
#define NWARP   (TPB / 32)
#define QT      4                  // queries per octet
#define QPW     (4 * QT)           // 16 queries per warp
#define QPB     (NWARP * QPW)      // 64 queries per block

typedef unsigned long long ull;

__constant__ int c_soff[NSPARSE] = {48,64,96,128,192,256,384,512,768,1024,1536};

// ---- packed f32x2 helpers (Blackwell FFMA2 path, PTX-only) ----
__device__ __forceinline__ ull f2fma(ull a, ull b, ull c) {
    ull d; asm("fma.rn.f32x2 %0, %1, %2, %3;" : "=l"(d) : "l"(a), "l"(b), "l"(c)); return d;
}
__device__ __forceinline__ ull f2add(ull a, ull b) {
    ull d; asm("add.rn.f32x2 %0, %1, %2;" : "=l"(d) : "l"(a), "l"(b)); return d;
}
__device__ __forceinline__ ull f2mul(ull a, ull b) {
    ull d; asm("mul.rn.f32x2 %0, %1, %2;" : "=l"(d) : "l"(a), "l"(b)); return d;
}
__device__ __forceinline__ ull f2pack(float lo, float hi) {
    ull d; asm("mov.b64 %0, {%1, %2};" : "=l"(d) : "f"(lo), "f"(hi)); return d;
}
__device__ __forceinline__ float2 f2unpack(ull v) {
    float lo, hi; asm("mov.b64 {%0, %1}, %2;" : "=f"(lo), "=f"(hi) : "l"(v));
    return make_float2(lo, hi);
}

__device__ __forceinline__ float dot8p(ulonglong2 qa, ulonglong2 qb,
                                       ulonglong2 b0, ulonglong2 b1) {
    ull acc = f2mul(qa.x, b0.x);
    acc = f2fma(qa.y, b0.y, acc);
    acc = f2fma(qb.x, b1.x, acc);
    acc = f2fma(qb.y, b1.y, acc);
    float2 r = f2unpack(acc);
    return r.x + r.y;
}

__device__ __forceinline__ ulonglong2 u2add(ulonglong2 a, ulonglong2 b) {
    ulonglong2 r; r.x = f2add(a.x, b.x); r.y = f2add(a.y, b.y); return r;
}

__device__ __forceinline__ float red8(float p) {
    p += __shfl_xor_sync(0xffffffffu, p, 1);
    p += __shfl_xor_sync(0xffffffffu, p, 2);
    p += __shfl_xor_sync(0xffffffffu, p, 4);
    return p;
}

__global__ __launch_bounds__(TPB, 4)
void dsqg_attn_kernel(const float* __restrict__ q,
                      const float* __restrict__ k,
                      const float* __restrict__ v,
                      const float* __restrict__ pb,
                      const float* __restrict__ se,
                      const float* __restrict__ ph,
                      float* __restrict__ out) {
    const int lane = threadIdx.x & 31;
    const int wid  = threadIdx.x >> 5;
    const int o    = lane >> 3;      // octet id (0..3)
    const int ln8  = lane & 7;       // lane within octet

    __shared__ ulonglong2 s_se[NOFF * 16];
    __shared__ float  s_pb[NOFF];
    __shared__ float  s_cos[NOFF];
    __shared__ float  s_sin[NOFF];
    // dense weights: float4 (wc,wc,ws,ws) per offset, UNION'd with raw scores
    // (pass 1 writes scores into the float view, cols 0..43 of the 132-float row)
    __shared__ float4 s_w4[QPB][NDENSE];        // 33.8 KB
    __shared__ float2 s_ws2[QPB][NSPARSE + 1];  // sparse (wc, ws), padded row

    for (int i = threadIdx.x; i < NOFF * 16; i += TPB)
        s_se[i] = ((const ulonglong2*)se)[i];
    if (threadIdx.x < NOFF) {
        const int h0 = blockIdx.y;
        s_pb[threadIdx.x] = pb[threadIdx.x * HNUM + h0];
        float p = ph[threadIdx.x * HNUM + h0];
        s_cos[threadIdx.x] = cosf(p);
        s_sin[threadIdx.x] = sinf(p);
    }
    __syncthreads();

    const int h = blockIdx.y;
    const int b = blockIdx.z;
    const size_t bh = ((size_t)b * HNUM + h) * SEQ;
    const ulonglong2* kb = (const ulonglong2*)(k + bh * HD);
    const ulonglong2* vb = (const ulonglong2*)(v + bh * HD);

    const int ql0 = wid * QPW + o * QT;
    const int n0  = blockIdx.x * QPB + ql0;
    const int n3  = n0 + 3;

    const float sc = 0.125f;   // 1/sqrt(64)

    // ================= pass 1: dense+sparse scores (4-deep k FIFO, packed) =================
    {
        ulonglong2 qa[QT], qbr[QT];
        #pragma unroll
        for (int t = 0; t < QT; t++) {
            const ulonglong2* qp = (const ulonglong2*)(q + (bh + (size_t)(n0 + t)) * HD);
            qa[t]  = qp[ln8];
            qbr[t] = qp[8 + ln8];
        }

        ulonglong2 f0[4], f1[4];
        #pragma unroll
        for (int j = 0; j < 4; j++) {
            const ulonglong2* kr = kb + (size_t)(n3 - j) * 16;
            f0[j] = kr[ln8];
            f1[j] = kr[8 + ln8];
        }
        #pragma unroll 3
        for (int d = 0; d < NDENSE; d++) {
            ulonglong2 e0 = s_se[d * 16 + ln8];
            ulonglong2 e1 = s_se[d * 16 + 8 + ln8];
            float p3 = dot8p(qa[3], qbr[3], u2add(f0[0], e0), u2add(f1[0], e1));
            float p2 = dot8p(qa[2], qbr[2], u2add(f0[1], e0), u2add(f1[1], e1));
            float p1 = dot8p(qa[1], qbr[1], u2add(f0[2], e0), u2add(f1[2], e1));
            float p0 = dot8p(qa[0], qbr[0], u2add(f0[3], e0), u2add(f1[3], e1));
            int rn = n0 - d - 1;
            int rc = rn < 0 ? 0 : rn;
            f0[0] = f0[1]; f1[0] = f1[1];
            f0[1] = f0[2]; f1[1] = f1[2];
            f0[2] = f0[3]; f1[2] = f1[3];
            {
                const ulonglong2* kr = kb + (size_t)rc * 16;
                f0[3] = kr[ln8];
                f1[3] = kr[8 + ln8];
            }
            p3 = red8(p3); p2 = red8(p2); p1 = red8(p1); p0 = red8(p0);
            if (ln8 == 0) {
                float bias = s_pb[d];
                ((float*)&s_w4[ql0 + 3][0])[d] = (n3     >= d) ? fmaf(p3, sc, bias) : -1e30f;
                ((float*)&s_w4[ql0 + 2][0])[d] = (n0 + 2 >= d) ? fmaf(p2, sc, bias) : -1e30f;
                ((float*)&s_w4[ql0 + 1][0])[d] = (n0 + 1 >= d) ? fmaf(p1, sc, bias) : -1e30f;
                ((float*)&s_w4[ql0    ][0])[d] = (n0     >= d) ? fmaf(p0, sc, bias) : -1e30f;
            }
        }

        #pragma unroll
        for (int i = 0; i < NSPARSE; i++) {
            const int d  = c_soff[i];
            const int io = NDENSE + i;
            ulonglong2 e0 = s_se[io * 16 + ln8];
            ulonglong2 e1 = s_se[io * 16 + 8 + ln8];
            float ps_[QT];
            #pragma unroll
            for (int t = 0; t < QT; t++) {
                int r  = n0 + t - d;
                int rc = r < 0 ? 0 : r;
                const ulonglong2* kr = kb + (size_t)rc * 16;
                ps_[t] = dot8p(qa[t], qbr[t], u2add(kr[ln8], e0), u2add(kr[8 + ln8], e1));
            }
            #pragma unroll
            for (int t = 0; t < QT; t++) ps_[t] = red8(ps_[t]);
            if (ln8 == 0) {
                float bias = s_pb[io];
                #pragma unroll
                for (int t = 0; t < QT; t++)
                    ((float*)&s_w4[ql0 + t][0])[io] = (n0 + t >= d) ? fmaf(ps_[t], sc, bias) : -1e30f;
            }
        }
    }
    __syncwarp();

    // ====== softmax (2 lanes/query, 22 offsets each) ======
    // dense -> float4 (wc,wc,ws,ws); sparse -> float2 (wc,ws).
    // Union safety: all score reads precede the first shfl; all writes follow the second.
    {
        const int qloc = wid * QPW + (lane & 15);
        const int half = lane >> 4;
        const int base = half * 22;
        float vals[22];
        float vmax = -FLT_MAX;
        #pragma unroll
        for (int t = 0; t < 22; t++) {
            vals[t] = ((const float*)&s_w4[qloc][0])[base + t];
            vmax = fmaxf(vmax, vals[t]);
        }
        vmax = fmaxf(vmax, __shfl_xor_sync(0xffffffffu, vmax, 16));
        float sum = 0.f;
        #pragma unroll
        for (int t = 0; t < 22; t++) {
            vals[t] = __expf(vals[t] - vmax);
            sum += vals[t];
        }
        sum += __shfl_xor_sync(0xffffffffu, sum, 16);
        const float inv = 1.0f / sum;
        #pragma unroll
        for (int t = 0; t < 22; t++) {
            const int d = base + t;
            float w  = vals[t] * inv;
            float wc = w * s_cos[d];
            float ws = w * s_sin[d];
            if (d < NDENSE)
                s_w4[qloc][d] = make_float4(wc, wc, ws, ws);
            else
                s_ws2[qloc][d - NDENSE] = make_float2(wc, ws);
        }
    }
    __syncwarp();

    // ========== pass 2: offset iteration, 4-deep v FIFO, A/B accumulate, rotate at end ==========
    ulonglong2 A0[QT], A1[QT], B0[QT], B1[QT];
    #pragma unroll
    for (int t = 0; t < QT; t++) {
        A0[t].x = A0[t].y = A1[t].x = A1[t].y = 0ull;
        B0[t].x = B0[t].y = B1[t].x = B1[t].y = 0ull;
    }

    // dense (4-deep FIFO; masked offsets have w == 0); weights pre-packed: LDS.128 -> FFMA2
    {
        ulonglong2 f0[4], f1[4];
        #pragma unroll
        for (int j = 0; j < 4; j++) {
            const ulonglong2* vr = vb + (size_t)(n3 - j) * 16;
            f0[j] = vr[ln8];
            f1[j] = vr[8 + ln8];
        }
        #pragma unroll 3
        for (int d = 0; d < NDENSE; d++) {
            #pragma unroll
            for (int t = 0; t < QT; t++) {
                ulonglong2 wp = *(const ulonglong2*)&s_w4[ql0 + t][d];  // (wc,wc | ws,ws)
                A0[t].x = f2fma(f0[3 - t].x, wp.x, A0[t].x);
                A0[t].y = f2fma(f0[3 - t].y, wp.x, A0[t].y);
                A1[t].x = f2fma(f1[3 - t].x, wp.x, A1[t].x);
                A1[t].y = f2fma(f1[3 - t].y, wp.x, A1[t].y);
                B0[t].x = f2fma(f0[3 - t].x, wp.y, B0[t].x);
                B0[t].y = f2fma(f0[3 - t].y, wp.y, B0[t].y);
                B1[t].x = f2fma(f1[3 - t].x, wp.y, B1[t].x);
                B1[t].y = f2fma(f1[3 - t].y, wp.y, B1[t].y);
            }
            int rn = n0 - d - 1;
            int rc = rn < 0 ? 0 : rn;
            f0[0] = f0[1]; f1[0] = f1[1];
            f0[1] = f0[2]; f1[1] = f1[2];
            f0[2] = f0[3]; f1[2] = f1[3];
            {
                const ulonglong2* vr = vb + (size_t)rc * 16;
                f0[3] = vr[ln8];
                f1[3] = vr[8 + ln8];
            }
        }
    }

    // sparse (w == 0 self-masks)
    #pragma unroll
    for (int i = 0; i < NSPARSE; i++) {
        const int d = c_soff[i];
        #pragma unroll
        for (int t = 0; t < QT; t++) {
            int r  = n0 + t - d;
            int rc = r < 0 ? 0 : r;
            float2 w = s_ws2[ql0 + t][i];
            ull pcp = f2pack(w.x, w.x);
            ull psp = f2pack(w.y, w.y);
            const ulonglong2* vr = vb + (size_t)rc * 16;
            ulonglong2 v0 = vr[ln8];
            ulonglong2 v1 = vr[8 + ln8];
            A0[t].x = f2fma(v0.x, pcp, A0[t].x);
            A0[t].y = f2fma(v0.y, pcp, A0[t].y);
            A1[t].x = f2fma(v1.x, pcp, A1[t].x);
            A1[t].y = f2fma(v1.y, pcp, A1[t].y);
            B0[t].x = f2fma(v0.x, psp, B0[t].x);
            B0[t].y = f2fma(v0.y, psp, B0[t].y);
            B1[t].x = f2fma(v1.x, psp, B1[t].x);
            B1[t].y = f2fma(v1.y, psp, B1[t].y);
        }
    }

    // ================= final rotation + store =================
    #pragma unroll
    for (int t = 0; t < QT; t++) {
        float4* op = (float4*)(out + (bh + (size_t)(n0 + t)) * HD);
        float2 a0 = f2unpack(A0[t].x), b0 = f2unpack(B0[t].x);
        float2 a1 = f2unpack(A0[t].y), b1 = f2unpack(B0[t].y);
        float2 a2 = f2unpack(A1[t].x), b2 = f2unpack(B1[t].x);
        float2 a3 = f2unpack(A1[t].y), b3 = f2unpack(B1[t].y);
        float4 r0, r1;
        r0.x = a0.x - b0.y;  r0.y = a0.y + b0.x;
        r0.z = a1.x - b1.y;  r0.w = a1.y + b1.x;
        r1.x = a2.x - b2.y;  r1.y = a2.y + b2.x;
        r1.z = a3.x - b3.y;  r1.w = a3.y + b3.x;
        op[ln8]     = r0;
        op[8 + ln8] = r1;
    }
}

extern "C" void kernel_launch(void* const* d_in, const int* in_sizes, int n_in,
                              void* d_out, int out_size) {
    const float* q  = (const float*)d_in[0];
    const float* k  = (const float*)d_in[1];
    const float* v  = (const float*)d_in[2];
    const float* pb = (const float*)d_in[3];
    const float* se = (const float*)d_in[4];
    const float* ph = (const float*)d_in[5];
    float* out = (float*)d_out;

    dim3 grid(SEQ / QPB, HNUM, BNUM);
    dsqg_attn_kernel<<<grid, TPB>>>(q, k, v, pb, se, ph, out);
}